// round 16
// baseline (speedup 1.0000x reference)
#include <cuda_runtime.h>
#include <cuda_fp16.h>
#include <cstdint>

#define NN 1024
#define BB 32
#define FF 32
#define DD 64
#define HH 64
#define CC 2048   // B*D
#define NP1 1025

// ---------------- scratch (static __device__, no allocs) ----------------
__device__ __half g_Ah[NN * NN];      // binarized adjacency, fp16 (exact 0/1)
__device__ float g_m13[NN * CC];      // mu_1 + mu3 + b2
__device__ float g_mu[NN * CC];       // final-round mu (fp32)
__device__ __half g_nuA[NN * CC];     // nu ping buffer (fp16)
__device__ __half g_nuB[NN * CC];     // nu pong buffer (fp16)
__device__ float g_part[8 * CC];      // column-sum partials (per 128-row mtile)

// ---------------- helpers ----------------
__device__ __forceinline__ uint32_t smem_u32(const void* p) {
    uint32_t a;
    asm("{ .reg .u64 t; cvta.to.shared.u64 t, %1; cvt.u32.u64 %0, t; }" : "=r"(a) : "l"(p));
    return a;
}
__device__ __forceinline__ void cp16(uint32_t saddr, const void* gaddr) {
    asm volatile("cp.async.cg.shared.global [%0], [%1], 16;\n" :: "r"(saddr), "l"(gaddr));
}

// ---------------- init: binarize adj + mu3 + mu_1 + m13 + first nu ----------------
__global__ __launch_bounds__(256) void k_init(const float* __restrict__ adj,
                                              const float* __restrict__ W4,
                                              const float* __restrict__ b4,
                                              const float* __restrict__ W3,
                                              const float* __restrict__ b3,
                                              const float* __restrict__ xv,
                                              const float* __restrict__ mu1w,
                                              const float* __restrict__ b2,
                                              const float* __restrict__ W2) {
    int n = blockIdx.x;
    int tid = threadIdx.x;
    __shared__ float arow[NN];
    __shared__ float part[4][DD];
    __shared__ float mu4s[DD];
    __shared__ float xs[BB][FF];
    __shared__ float ws[FF][DD];
    __shared__ float m3[DD];
    __shared__ float mus[CC];
    __shared__ float4 W2q[16 * 64];   // [e4][d]

    {
        float4 v = ((const float4*)(adj + (size_t)n * NN))[tid];
        arow[tid * 4 + 0] = v.x;
        arow[tid * 4 + 1] = v.y;
        arow[tid * 4 + 2] = v.z;
        arow[tid * 4 + 3] = v.w;
        union { uint2 u; __half h[4]; } pk;
        pk.h[0] = __float2half(v.x > 0.f ? 1.f : 0.f);
        pk.h[1] = __float2half(v.y > 0.f ? 1.f : 0.f);
        pk.h[2] = __float2half(v.z > 0.f ? 1.f : 0.f);
        pk.h[3] = __float2half(v.w > 0.f ? 1.f : 0.f);
        *(uint2*)(g_Ah + (size_t)n * NN + tid * 4) = pk.u;
    }
    for (int i = tid; i < BB * FF; i += 256) {
        int b = i / FF, f = i % FF;
        xs[b][f] = xv[(b * NN + n) * FF + f];
    }
    for (int i = tid; i < FF * DD; i += 256) ws[i / DD][i % DD] = mu1w[i];
    for (int i = tid; i < 1024; i += 256) {
        int d = i >> 4, e4 = i & 15;
        W2q[e4 * 64 + d] = ((const float4*)(W2 + d * DD))[e4];
    }
    __syncthreads();

    {
        int d = tid & 63, q = tid >> 6;
        float w = W4[d], c0 = b4[d];
        float a0 = 0.f, a1 = 0.f, a2 = 0.f, a3 = 0.f;
        for (int m = q; m < NN; m += 16) {
            a0 += fmaxf(arow[m]      * w + c0, 0.f);
            a1 += fmaxf(arow[m + 4]  * w + c0, 0.f);
            a2 += fmaxf(arow[m + 8]  * w + c0, 0.f);
            a3 += fmaxf(arow[m + 12] * w + c0, 0.f);
        }
        part[q][d] = (a0 + a1) + (a2 + a3);
    }
    __syncthreads();
    if (tid < DD) mu4s[tid] = part[0][tid] + part[1][tid] + part[2][tid] + part[3][tid];
    __syncthreads();
    {
        int d2 = tid & 63, q2 = tid >> 6;
        float a = 0.f;
#pragma unroll
        for (int e = 0; e < 16; e++)
            a += mu4s[q2 * 16 + e] * W3[d2 * DD + q2 * 16 + e];
        part[q2][d2] = a;
    }
    __syncthreads();
    if (tid < DD)
        m3[tid] = b3[tid] + b2[tid] + part[0][tid] + part[1][tid] + part[2][tid] + part[3][tid];
    __syncthreads();

#pragma unroll
    for (int j = 0; j < 8; j++) {
        int c = tid + 256 * j;
        int b = c >> 6, d = c & 63;
        float acc = 0.f;
#pragma unroll
        for (int f = 0; f < FF; f++) acc += xs[b][f] * ws[f][d];
        float r = fmaxf(acc, 0.f);
        g_m13[n * CC + c] = r + m3[d];
        mus[c] = r;
    }
    __syncthreads();

    int b = tid >> 3, dg = tid & 7;
    const float4* mb = (const float4*)(mus + b * DD);
    float acc[8] = {};
#pragma unroll
    for (int e4 = 0; e4 < 16; e4++) {
        float4 m = mb[e4];
#pragma unroll
        for (int k = 0; k < 8; k++) {
            float4 w = W2q[e4 * 64 + k * 8 + dg];
            acc[k] += m.x * w.x + m.y * w.y + m.z * w.z + m.w * w.w;
        }
    }
    size_t base = (size_t)n * CC + b * DD + dg;
#pragma unroll
    for (int k = 0; k < 8; k++)
        g_nuA[base + k * 8] = __float2half(acc[k]);
}

// ---------------- pool = A @ nu via mma.sync fp16; 3-stage, 1 barrier/chunk ----------------
// CTA tile 128(m) x 64(c). 8 warps (4Mx2N), 2 CTAs/SM. All 8 LDSM of a chunk are
// hoisted ahead of the 32 MMAs so the second ks-group's fragment latency hides
// under the first group's tensor work.
__global__ __launch_bounds__(256, 2) void k_mma(int mode, const float* __restrict__ W2,
                                                const __half* __restrict__ nin,
                                                __half* __restrict__ nout) {
    __shared__ __align__(16) char SB[49152];  // stages: 3 x 12KB at 0/12288/24576

    int tid = threadIdx.x;
    int lane = tid & 31, wid = tid >> 5;
    int warpM = wid >> 1, warpN = wid & 1;   // 4 x 2 warps; warp tile 32(m) x 32(c)
    int mbase = blockIdx.y * 128;
    int cbase = blockIdx.x * 64;

    uint32_t sb0 = smem_u32(SB);
    uint32_t asb[3] = { sb0, sb0 + 12288, sb0 + 24576 };         // A: 8KB
    uint32_t bsb[3] = { sb0 + 8192, sb0 + 20480, sb0 + 32768 };  // B: 4KB

    // hoisted ldmatrix offsets (loop-invariant swizzle math)
    uint32_t aoff[2][2], boff[2][2];
#pragma unroll
    for (int ks = 0; ks < 2; ks++) {
#pragma unroll
        for (int mt = 0; mt < 2; mt++) {
            int row = warpM * 32 + mt * 16 + (lane & 7) + ((lane >> 3) & 1) * 8;
            int unit = 2 * ks + (lane >> 4);
            aoff[ks][mt] = row * 64 + (((unit ^ ((row >> 1) & 3)) & 3) << 4);
        }
#pragma unroll
        for (int pair = 0; pair < 2; pair++) {
            int k = ks * 16 + (lane & 7) + ((lane >> 3) & 1) * 8;
            int u = warpN * 4 + pair * 2 + (lane >> 4);
            int su = (u ^ k) & 7;
            boff[ks][pair] = k * 128 + (su << 4);
        }
    }

    float C[8][4];
#pragma unroll
    for (int i = 0; i < 8; i++)
#pragma unroll
        for (int j = 0; j < 4; j++) C[i][j] = 0.f;

    // hoisted load addressing
    int la_m = tid >> 2, la_u = tid & 3;
    const __half* gA = g_Ah + (size_t)(mbase + la_m) * NN + la_u * 8;
    const __half* gA2 = g_Ah + (size_t)(mbase + la_m + 64) * NN + la_u * 8;
    uint32_t sA = la_m * 64 + (((la_u ^ ((la_m >> 1) & 3)) & 3) << 4);
    uint32_t sA2 = (la_m + 64) * 64 + (((la_u ^ (((la_m + 64) >> 1) & 3)) & 3) << 4);
    int lb_k = tid >> 3, lb_u = tid & 7;
    const __half* gB = nin + (size_t)lb_k * CC + cbase + lb_u * 8;
    uint32_t sBo = lb_k * 128 + ((((lb_u ^ lb_k) & 7)) << 4);

    auto load_stage = [&](int ch, int buf) {
        cp16(asb[buf] + sA, gA + ch * 32);
        cp16(asb[buf] + sA2, gA2 + ch * 32);
        cp16(bsb[buf] + sBo, gB + (size_t)ch * 32 * CC);
        asm volatile("cp.async.commit_group;\n" ::: "memory");
    };

    load_stage(0, 0);
    load_stage(1, 1);

    for (int ch = 0; ch < 32; ch++) {
        int buf = ch % 3;
        if (ch + 1 < 32) asm volatile("cp.async.wait_group 1;\n" ::: "memory");
        else             asm volatile("cp.async.wait_group 0;\n" ::: "memory");
        __syncthreads();
        // load AFTER the barrier: targets buf (ch+2)%3 == (ch-1)%3, which every
        // thread finished reading (compute of ch-1) before arriving here.
        if (ch + 2 < 32) load_stage(ch + 2, (ch + 2) % 3);

        // --- hoist ALL fragment loads for this chunk ---
        uint32_t a[2][2][4];
        uint32_t bf[2][4][2];
#pragma unroll
        for (int ks = 0; ks < 2; ks++) {
#pragma unroll
            for (int mt = 0; mt < 2; mt++) {
                asm volatile("ldmatrix.sync.aligned.m8n8.x4.shared.b16 {%0,%1,%2,%3}, [%4];"
                             : "=r"(a[ks][mt][0]), "=r"(a[ks][mt][1]),
                               "=r"(a[ks][mt][2]), "=r"(a[ks][mt][3])
                             : "r"(asb[buf] + aoff[ks][mt]));
            }
#pragma unroll
            for (int pair = 0; pair < 2; pair++) {
                asm volatile("ldmatrix.sync.aligned.m8n8.x4.trans.shared.b16 {%0,%1,%2,%3}, [%4];"
                             : "=r"(bf[ks][pair * 2][0]), "=r"(bf[ks][pair * 2][1]),
                               "=r"(bf[ks][pair * 2 + 1][0]), "=r"(bf[ks][pair * 2 + 1][1])
                             : "r"(bsb[buf] + boff[ks][pair]));
            }
        }
        // --- all 32 MMAs ---
#pragma unroll
        for (int ks = 0; ks < 2; ks++) {
#pragma unroll
            for (int mt = 0; mt < 2; mt++) {
#pragma unroll
                for (int nt = 0; nt < 4; nt++) {
                    float* c = C[mt * 4 + nt];
                    asm volatile(
                        "mma.sync.aligned.m16n8k16.row.col.f32.f16.f16.f32 "
                        "{%0,%1,%2,%3},{%4,%5,%6,%7},{%8,%9},{%0,%1,%2,%3};"
                        : "+f"(c[0]), "+f"(c[1]), "+f"(c[2]), "+f"(c[3])
                        : "r"(a[ks][mt][0]), "r"(a[ks][mt][1]),
                          "r"(a[ks][mt][2]), "r"(a[ks][mt][3]),
                          "r"(bf[ks][nt][0]), "r"(bf[ks][nt][1]));
                }
            }
        }
    }
    // protect SB reuse below against warps still reading the last stage buffers
    __syncthreads();

    int g = lane >> 2, tq = lane & 3;

    if (mode == 0) {
        // ---- epilogue: mu = relu(m13 + pool) -> hi/lo fp16 smem; nu via MMA ----
        char* muh = (char*)SB;
        char* mul = (char*)SB + 16384;
        char* w2h = (char*)SB + 32768;
        char* w2l = (char*)SB + 40960;
        for (int i = tid; i < 1024; i += 256) {
            int d = i >> 4, e4 = i & 15;
            float4 w = ((const float4*)(W2 + d * DD))[e4];
            int u = e4 >> 1;
            int su = (u ^ (d & 7)) & 7;
            uint32_t off = d * 128 + su * 16 + (e4 & 1) * 8;
            __half hx = __float2half(w.x), hy = __float2half(w.y);
            __half hz = __float2half(w.z), hw = __float2half(w.w);
            union { uint2 u2; __half2 h[2]; } ph, pl;
            ph.h[0] = __halves2half2(hx, hy);
            ph.h[1] = __halves2half2(hz, hw);
            pl.h[0] = __floats2half2_rn(w.x - __half2float(hx), w.y - __half2float(hy));
            pl.h[1] = __floats2half2_rn(w.z - __half2float(hz), w.w - __half2float(hw));
            *(uint2*)(w2h + off) = ph.u2;
            *(uint2*)(w2l + off) = pl.u2;
        }
#pragma unroll
        for (int mt = 0; mt < 2; mt++) {
#pragma unroll
            for (int nt = 0; nt < 4; nt++) {
                const float* c = C[mt * 4 + nt];
                int rl0 = warpM * 32 + mt * 16 + g;
                int cl = warpN * 32 + nt * 8 + tq * 2;
                int u = cl >> 3, wo = (cl & 7) * 2;
#pragma unroll
                for (int half = 0; half < 2; half++) {
                    int rl = rl0 + half * 8;
                    const float2 m = *(const float2*)(g_m13 + (size_t)(mbase + rl) * CC + cbase + cl);
                    float vx = fmaxf(m.x + c[half * 2 + 0], 0.f);
                    float vy = fmaxf(m.y + c[half * 2 + 1], 0.f);
                    __half hx = __float2half(vx), hy = __float2half(vy);
                    int su = (u ^ (rl & 7)) & 7;
                    uint32_t off = rl * 128 + su * 16 + wo;
                    *(__half2*)(muh + off) = __halves2half2(hx, hy);
                    *(__half2*)(mul + off) = __floats2half2_rn(vx - __half2float(hx),
                                                               vy - __half2float(hy));
                }
            }
        }
        __syncthreads();

        int mrow = wid * 16;
        uint32_t afh[4][4], afl[4][4];
#pragma unroll
        for (int ks = 0; ks < 4; ks++) {
            int row = mrow + (lane & 7) + ((lane >> 3) & 1) * 8;
            int unit = 2 * ks + (lane >> 4);
            int su = (unit ^ (row & 7)) & 7;
            uint32_t off = row * 128 + su * 16;
            asm volatile("ldmatrix.sync.aligned.m8n8.x4.shared.b16 {%0,%1,%2,%3}, [%4];"
                         : "=r"(afh[ks][0]), "=r"(afh[ks][1]), "=r"(afh[ks][2]), "=r"(afh[ks][3])
                         : "r"(sb0 + off));
            asm volatile("ldmatrix.sync.aligned.m8n8.x4.shared.b16 {%0,%1,%2,%3}, [%4];"
                         : "=r"(afl[ks][0]), "=r"(afl[ks][1]), "=r"(afl[ks][2]), "=r"(afl[ks][3])
                         : "r"(sb0 + 16384 + off));
        }
#define NU_MMA(cacc, AH, B0, B1) \
    asm volatile("mma.sync.aligned.m16n8k16.row.col.f32.f16.f16.f32 " \
                 "{%0,%1,%2,%3},{%4,%5,%6,%7},{%8,%9},{%0,%1,%2,%3};" \
                 : "+f"(cacc[0]), "+f"(cacc[1]), "+f"(cacc[2]), "+f"(cacc[3]) \
                 : "r"(AH[0]), "r"(AH[1]), "r"(AH[2]), "r"(AH[3]), "r"(B0), "r"(B1))
#pragma unroll
        for (int pair = 0; pair < 4; pair++) {
            float c0[4] = {}, c1[4] = {};
#pragma unroll
            for (int ks = 0; ks < 4; ks++) {
                int row = pair * 16 + (lane & 7) + ((lane >> 3) & 1) * 8;
                int unit = 2 * ks + (lane >> 4);
                int su = (unit ^ (row & 7)) & 7;
                uint32_t off = row * 128 + su * 16;
                uint32_t bh0, bh1, bh2, bh3, bl0, bl1, bl2, bl3;
                asm volatile("ldmatrix.sync.aligned.m8n8.x4.shared.b16 {%0,%1,%2,%3}, [%4];"
                             : "=r"(bh0), "=r"(bh1), "=r"(bh2), "=r"(bh3) : "r"(sb0 + 32768 + off));
                asm volatile("ldmatrix.sync.aligned.m8n8.x4.shared.b16 {%0,%1,%2,%3}, [%4];"
                             : "=r"(bl0), "=r"(bl1), "=r"(bl2), "=r"(bl3) : "r"(sb0 + 40960 + off));
                NU_MMA(c0, afh[ks], bh0, bh2);
                NU_MMA(c0, afh[ks], bl0, bl2);
                NU_MMA(c0, afl[ks], bh0, bh2);
                NU_MMA(c1, afh[ks], bh1, bh3);
                NU_MMA(c1, afh[ks], bl1, bl3);
                NU_MMA(c1, afl[ks], bh1, bh3);
            }
            size_t grow = (size_t)(mbase + mrow + g);
            int col0 = cbase + pair * 16 + tq * 2;
            *(__half2*)(nout + grow * CC + col0)           = __floats2half2_rn(c0[0], c0[1]);
            *(__half2*)(nout + (grow + 8) * CC + col0)     = __floats2half2_rn(c0[2], c0[3]);
            *(__half2*)(nout + grow * CC + col0 + 8)       = __floats2half2_rn(c1[0], c1[1]);
            *(__half2*)(nout + (grow + 8) * CC + col0 + 8) = __floats2half2_rn(c1[2], c1[3]);
        }
#undef NU_MMA
    } else {
        // ---- final round: mu -> global, plus column-sum partials ----
#pragma unroll
        for (int mt = 0; mt < 2; mt++) {
#pragma unroll
            for (int nt = 0; nt < 4; nt++) {
                const float* c = C[mt * 4 + nt];
                int row0 = mbase + warpM * 32 + mt * 16 + g;
                int col = cbase + warpN * 32 + nt * 8 + tq * 2;
                {
                    const float2 m = *(const float2*)(g_m13 + (size_t)row0 * CC + col);
                    float2 o;
                    o.x = fmaxf(m.x + c[0], 0.f);
                    o.y = fmaxf(m.y + c[1], 0.f);
                    *(float2*)(g_mu + (size_t)row0 * CC + col) = o;
                }
                {
                    int row1 = row0 + 8;
                    const float2 m = *(const float2*)(g_m13 + (size_t)row1 * CC + col);
                    float2 o;
                    o.x = fmaxf(m.x + c[2], 0.f);
                    o.y = fmaxf(m.y + c[3], 0.f);
                    *(float2*)(g_mu + (size_t)row1 * CC + col) = o;
                }
            }
        }
        float* cs = (float*)SB;
        __syncthreads();
        int c = tid & 63, q = tid >> 6;
        const float* mp = g_mu + (size_t)(mbase + q * 32) * CC + cbase + c;
        float s = 0.f;
#pragma unroll 8
        for (int r = 0; r < 32; r++) s += mp[(size_t)r * CC];
        cs[q * 64 + c] = s;
        __syncthreads();
        if (tid < 64)
            g_part[blockIdx.y * CC + cbase + tid] =
                cs[tid] + cs[64 + tid] + cs[128 + tid] + cs[192 + tid];
    }
}

// ---------------- final head (fused mumean + s2; float4 LDS) ----------------
__global__ __launch_bounds__(256) void k_final(const float* __restrict__ Wreg,
                                               const float* __restrict__ breg,
                                               const float* __restrict__ Wq,
                                               const float* __restrict__ bq,
                                               const float* __restrict__ option,
                                               const float* __restrict__ Wq1,
                                               const float* __restrict__ bq1,
                                               const float* __restrict__ Wq2,
                                               const float* __restrict__ bq2,
                                               float* __restrict__ out) {
    int b = blockIdx.y;
    int tile = blockIdx.x;
    __shared__ float Wr[HH][DD + 4];   // 272B stride: float4-aligned, conflict-free
    __shared__ float wqs[HH], s2s[HH], brs[HH];
    __shared__ float vs[8][DD];
    __shared__ float msum[DD];
    __shared__ float mm[DD];           // mumean for this b
    int tid = threadIdx.x;
    for (int i = tid; i < HH * DD; i += 256) {
        int h = i >> 6, j = i & 63;
        Wr[h][j] = Wreg[h * (2 * DD) + j];
    }
    if (tid < HH) {
        wqs[tid] = Wq[tid];
        brs[tid] = breg[tid];
    }
    // msum for this b from pooling partials
    if (tid >= 64 && tid < 128) {
        int d = tid - 64;
        float s = 0.f;
#pragma unroll
        for (int g2 = 0; g2 < 8; g2++) s += g_part[g2 * CC + b * DD + d];
        msum[d] = s * (1.0f / (float)NN);
    }
    __syncthreads();
    if (tid < DD) {   // mumean
        float acc = bq1[tid];
#pragma unroll
        for (int e = 0; e < DD; e++) acc += msum[e] * Wq1[tid * DD + e];
        mm[tid] = fmaxf(acc, 0.f);
    } else if (tid >= 64 && tid < 128) {   // s2
        int h = tid - 64;
        float opt = option[b];
        float acc2 = 0.f;
#pragma unroll
        for (int j = 0; j < DD; j++)
            acc2 += (opt * Wq2[j] + bq2[j]) * Wreg[h * (2 * DD) + DD + j];
        s2s[h] = acc2;
    }
    __syncthreads();
    int w = tid >> 5, lane = tid & 31;
    float bqv = bq[0];
    for (int s = 0; s < 8; s++) {
        int i = tile * 64 + w * 8 + s;
        if (i > NN) continue;
        const float* vptr = (i < NN) ? (g_mu + (size_t)i * CC + b * DD) : mm;
        vs[w][lane]      = vptr[lane];
        vs[w][lane + 32] = vptr[lane + 32];
        __syncwarp();
        float r = 0.f;
        const float4* v4 = (const float4*)vs[w];
#pragma unroll
        for (int hh = 0; hh < 2; hh++) {
            int h = lane + hh * 32;
            float accd = s2s[h] + brs[h];
            const float4* w4 = (const float4*)Wr[h];
#pragma unroll
            for (int e = 0; e < 16; e++) {
                float4 vv = v4[e];
                float4 ww = w4[e];
                accd += vv.x * ww.x + vv.y * ww.y + vv.z * ww.z + vv.w * ww.w;
            }
            r += fmaxf(accd, 0.f) * wqs[h];
        }
#pragma unroll
        for (int off = 16; off; off >>= 1) r += __shfl_down_sync(0xffffffff, r, off);
        if (lane == 0) out[b * NP1 + i] = r + bqv;
        __syncwarp();
    }
}

// ---------------- launch ----------------
extern "C" void kernel_launch(void* const* d_in, const int* in_sizes, int n_in,
                              void* d_out, int out_size) {
    const float* xv     = (const float*)d_in[0];
    const float* option = (const float*)d_in[1];
    const float* adj    = (const float*)d_in[2];
    const float* mu1w   = (const float*)d_in[3];
    const float* W2     = (const float*)d_in[4];
    const float* b2     = (const float*)d_in[5];
    const float* W3     = (const float*)d_in[6];
    const float* b3     = (const float*)d_in[7];
    const float* W4     = (const float*)d_in[8];
    const float* b4     = (const float*)d_in[9];
    const float* Wq1    = (const float*)d_in[10];
    const float* bq1    = (const float*)d_in[11];
    const float* Wq2    = (const float*)d_in[12];
    const float* bq2    = (const float*)d_in[13];
    const float* Wreg   = (const float*)d_in[14];
    const float* breg   = (const float*)d_in[15];
    const float* Wq     = (const float*)d_in[16];
    const float* bq     = (const float*)d_in[17];
    float* out = (float*)d_out;
    (void)in_sizes; (void)n_in; (void)out_size;

    static __half *nuA = nullptr, *nuB = nullptr;
    if (!nuA) {
        cudaGetSymbolAddress((void**)&nuA, g_nuA);
        cudaGetSymbolAddress((void**)&nuB, g_nuB);
    }

    k_init<<<NN, 256>>>(adj, W4, b4, W3, b3, xv, mu1w, b2, W2);
    k_mma<<<dim3(CC / 64, NN / 128), 256>>>(0, W2, nuA, nuB);     // t=1: A->B
    k_mma<<<dim3(CC / 64, NN / 128), 256>>>(0, W2, nuB, nuA);     // t=2: B->A
    k_mma<<<dim3(CC / 64, NN / 128), 256>>>(1, W2, nuA, nullptr); // t=3
    k_final<<<dim3(17, BB), 256>>>(Wreg, breg, Wq, bq, option, Wq1, bq1, Wq2, bq2, out);
}